// round 1
// baseline (speedup 1.0000x reference)
#include <cuda_runtime.h>
#include <cuda_bf16.h>
#include <math.h>

// Problem constants
#define B  4
#define S  4096
#define H  1024
#define NH 16
#define D  64
#define SCALE 0.125f            // 1/sqrt(64)

#define GM (B*S)   // 16384
#define GN H       // 1024
#define GK H       // 1024

#define CTX_ELEMS ((size_t)B * S * H)   // 16777216

// Scratch for q, k, v (device globals: allocation-free)
__device__ float g_q[B * S * H];
__device__ float g_k[B * S * H];
__device__ float g_v[B * S * H];

// ---------------------------------------------------------------------------
// Fused QKV GEMM:  C = A @ W^T + bias, for W in {Wq,Wk,Wv} selected by blockIdx.z
// A: [GM, GK] row-major (hidden). W: [GN, GK] row-major (so W^T needs K-contig
// reads from both — ideal). Classic 128x128x8 tile, 256 threads, 8x8 per thread.
// ---------------------------------------------------------------------------
#define BM 128
#define BN 128
#define BK 8

__global__ __launch_bounds__(256) void qkv_gemm(
    const float* __restrict__ A,
    const float* __restrict__ Wq, const float* __restrict__ Bq,
    const float* __restrict__ Wk, const float* __restrict__ Bk,
    const float* __restrict__ Wv, const float* __restrict__ Bv)
{
    const float* W;
    const float* bias;
    float* C;
    if (blockIdx.z == 0)      { W = Wq; bias = Bq; C = g_q; }
    else if (blockIdx.z == 1) { W = Wk; bias = Bk; C = g_k; }
    else                      { W = Wv; bias = Bv; C = g_v; }

    const int bm = blockIdx.y * BM;
    const int bn = blockIdx.x * BN;

    __shared__ float As[BK][BM];
    __shared__ float Bs[BK][BN];

    const int tid  = threadIdx.x;
    const int lrow = tid >> 1;          // 0..127
    const int lk   = (tid & 1) * 4;     // 0 or 4
    const int tm0  = (tid >> 4) * 8;    // 0,8,...,120
    const int tn0  = (tid & 15) * 8;

    float acc[8][8];
    #pragma unroll
    for (int i = 0; i < 8; i++)
        #pragma unroll
        for (int j = 0; j < 8; j++) acc[i][j] = 0.f;

    const float* Aptr = A + (size_t)(bm + lrow) * GK + lk;
    const float* Wptr = W + (size_t)(bn + lrow) * GK + lk;

    for (int kt = 0; kt < GK; kt += BK) {
        float4 a4 = *(const float4*)(Aptr + kt);
        float4 w4 = *(const float4*)(Wptr + kt);
        As[lk + 0][lrow] = a4.x;
        As[lk + 1][lrow] = a4.y;
        As[lk + 2][lrow] = a4.z;
        As[lk + 3][lrow] = a4.w;
        Bs[lk + 0][lrow] = w4.x;
        Bs[lk + 1][lrow] = w4.y;
        Bs[lk + 2][lrow] = w4.z;
        Bs[lk + 3][lrow] = w4.w;
        __syncthreads();

        #pragma unroll
        for (int kk = 0; kk < BK; kk++) {
            float a[8], bb[8];
            *(float4*)(a)      = *(const float4*)&As[kk][tm0];
            *(float4*)(a + 4)  = *(const float4*)&As[kk][tm0 + 4];
            *(float4*)(bb)     = *(const float4*)&Bs[kk][tn0];
            *(float4*)(bb + 4) = *(const float4*)&Bs[kk][tn0 + 4];
            #pragma unroll
            for (int i = 0; i < 8; i++)
                #pragma unroll
                for (int j = 0; j < 8; j++)
                    acc[i][j] = fmaf(a[i], bb[j], acc[i][j]);
        }
        __syncthreads();
    }

    // Epilogue: add bias, store
    float bv[8];
    #pragma unroll
    for (int j = 0; j < 8; j++) bv[j] = bias[bn + tn0 + j];

    #pragma unroll
    for (int i = 0; i < 8; i++) {
        size_t row = (size_t)(bm + tm0 + i);
        float* crow = C + row * GN + bn + tn0;
        float4 o0, o1;
        o0.x = acc[i][0] + bv[0]; o0.y = acc[i][1] + bv[1];
        o0.z = acc[i][2] + bv[2]; o0.w = acc[i][3] + bv[3];
        o1.x = acc[i][4] + bv[4]; o1.y = acc[i][5] + bv[5];
        o1.z = acc[i][6] + bv[6]; o1.w = acc[i][7] + bv[7];
        ((float4*)crow)[0] = o0;
        ((float4*)crow)[1] = o1;
    }
}

// ---------------------------------------------------------------------------
// Global attention: one block per (b,h). Query at s=0 attends to all S keys.
// Scores kept in smem, block softmax, weighted V sum.
// ---------------------------------------------------------------------------
__global__ __launch_bounds__(1024) void global_attn(
    const float* __restrict__ mask, float* __restrict__ out)
{
    const int bh = blockIdx.x;
    const int b  = bh / NH;
    const int h  = bh % NH;

    __shared__ float sq[D];
    __shared__ float scores[S];        // 16KB
    __shared__ float red[32];
    __shared__ float pacc[32][65];     // padded to dodge bank conflicts

    const int tid  = threadIdx.x;
    const int lane = tid & 31;
    const int w    = tid >> 5;

    const float* qbase = g_q + ((size_t)b * S + 0) * H + h * D;
    if (tid < D) sq[tid] = qbase[tid];
    __syncthreads();

    // scores[s] = (gq . k_s) * SCALE + mask[b,s]
    for (int s = tid; s < S; s += 1024) {
        const float4* krow = (const float4*)(g_k + ((size_t)b * S + s) * H + h * D);
        float acc = 0.f;
        #pragma unroll
        for (int i = 0; i < 16; i++) {
            float4 kv = krow[i];
            acc = fmaf(kv.x, sq[4*i+0], acc);
            acc = fmaf(kv.y, sq[4*i+1], acc);
            acc = fmaf(kv.z, sq[4*i+2], acc);
            acc = fmaf(kv.w, sq[4*i+3], acc);
        }
        scores[s] = acc * SCALE + mask[(size_t)b * S + s];
    }
    __syncthreads();

    // block max
    float lm = -INFINITY;
    for (int s = tid; s < S; s += 1024) lm = fmaxf(lm, scores[s]);
    #pragma unroll
    for (int o = 16; o; o >>= 1) lm = fmaxf(lm, __shfl_xor_sync(~0u, lm, o));
    if (lane == 0) red[w] = lm;
    __syncthreads();
    if (w == 0) {
        float v = red[lane];
        #pragma unroll
        for (int o = 16; o; o >>= 1) v = fmaxf(v, __shfl_xor_sync(~0u, v, o));
        if (lane == 0) red[0] = v;
    }
    __syncthreads();
    const float m = red[0];
    __syncthreads();

    // exp + sum
    float ls = 0.f;
    for (int s = tid; s < S; s += 1024) {
        float p = expf(scores[s] - m);
        scores[s] = p;
        ls += p;
    }
    #pragma unroll
    for (int o = 16; o; o >>= 1) ls += __shfl_xor_sync(~0u, ls, o);
    if (lane == 0) red[w] = ls;
    __syncthreads();
    if (w == 0) {
        float v = red[lane];
        #pragma unroll
        for (int o = 16; o; o >>= 1) v += __shfl_xor_sync(~0u, v, o);
        if (lane == 0) red[0] = v;
    }
    __syncthreads();
    const float denom = red[0];

    // weighted V sum: warp w covers s in [w*128, w*128+128), lane owns dims 2*lane,2*lane+1
    float acc0 = 0.f, acc1 = 0.f;
    const int s0 = w * (S / 32);
    for (int i = 0; i < S / 32; i++) {
        int s = s0 + i;
        float p = scores[s];
        float2 v2 = ((const float2*)(g_v + ((size_t)b * S + s) * H + h * D))[lane];
        acc0 = fmaf(p, v2.x, acc0);
        acc1 = fmaf(p, v2.y, acc1);
    }
    pacc[w][2*lane]   = acc0;
    pacc[w][2*lane+1] = acc1;
    __syncthreads();

    if (tid < D) {
        float sum = 0.f;
        #pragma unroll
        for (int ww = 0; ww < 32; ww++) sum += pacc[ww][tid];
        out[((size_t)b * S + 0) * H + h * D + tid] = sum / denom;
    }
}

// ---------------------------------------------------------------------------
// Local attention: one warp per (b, h, s) for s in 1..S-1.
// 2-way softmax over {self, global} scores; write l_out (into ctx) and l_attn.
// ---------------------------------------------------------------------------
__global__ __launch_bounds__(256) void local_attn(float* __restrict__ out)
{
    const int gwarp = (blockIdx.x * blockDim.x + threadIdx.x) >> 5;
    const int lane  = threadIdx.x & 31;
    const int total = B * NH * (S - 1);
    if (gwarp >= total) return;

    const int s1 = gwarp % (S - 1);
    const int s  = s1 + 1;
    const int bh = gwarp / (S - 1);
    const int h  = bh % NH;
    const int b  = bh / NH;

    const size_t base_s = ((size_t)b * S + s) * H + (size_t)h * D;
    const size_t base_0 = ((size_t)b * S + 0) * H + (size_t)h * D;

    float2 q2 = ((const float2*)(g_q + base_s))[lane];
    float2 k2 = ((const float2*)(g_k + base_s))[lane];
    float2 k0 = ((const float2*)(g_k + base_0))[lane];

    float ps = q2.x * k2.x + q2.y * k2.y;   // self
    float pg = q2.x * k0.x + q2.y * k0.y;   // global
    #pragma unroll
    for (int o = 16; o; o >>= 1) {
        ps += __shfl_xor_sync(~0u, ps, o);
        pg += __shfl_xor_sync(~0u, pg, o);
    }
    ps *= SCALE;
    pg *= SCALE;

    float m  = fmaxf(ps, pg);
    float e0 = expf(ps - m);
    float e1 = expf(pg - m);
    float inv = 1.f / (e0 + e1);
    float p0 = e0 * inv;     // weight on v_self
    float p1 = e1 * inv;     // weight on v_global

    float2 v2 = ((const float2*)(g_v + base_s))[lane];
    float2 v0 = ((const float2*)(g_v + base_0))[lane];
    float2 o2;
    o2.x = p0 * v2.x + p1 * v0.x;
    o2.y = p0 * v2.y + p1 * v0.y;
    ((float2*)(out + base_s))[lane] = o2;

    if (lane == 0) {
        size_t li = CTX_ELEMS + ((size_t)bh * (S - 1) + s1) * 2;
        out[li]     = p0;
        out[li + 1] = p1;
    }
}

// ---------------------------------------------------------------------------
extern "C" void kernel_launch(void* const* d_in, const int* in_sizes, int n_in,
                              void* d_out, int out_size)
{
    const float* hidden = (const float*)d_in[0];
    const float* mask   = (const float*)d_in[1];
    const float* Wq     = (const float*)d_in[2];
    const float* bq     = (const float*)d_in[3];
    const float* Wk     = (const float*)d_in[4];
    const float* bk     = (const float*)d_in[5];
    const float* Wv     = (const float*)d_in[6];
    const float* bv     = (const float*)d_in[7];
    float* out = (float*)d_out;

    dim3 ggrid(GN / BN, GM / BM, 3);   // (8, 128, 3)
    qkv_gemm<<<ggrid, 256>>>(hidden, Wq, bq, Wk, bk, Wv, bv);

    global_attn<<<B * NH, 1024>>>(mask, out);

    const int totalWarps = B * NH * (S - 1);          // 262080
    const int blocks = (totalWarps * 32 + 255) / 256; // 32760
    local_attn<<<blocks, 256>>>(out);
}

// round 3
// speedup vs baseline: 3.0591x; 3.0591x over previous
#include <cuda_runtime.h>
#include <cuda_bf16.h>
#include <math.h>
#include <cstdint>

// ---------------------------------------------------------------------------
// Problem constants
// ---------------------------------------------------------------------------
#define B  4
#define S  4096
#define H  1024
#define NH 16
#define D  64
#define SCALE 0.125f

#define GM (B*S)   // 16384
#define GN H       // 1024
#define GK H       // 1024

#define CTX_ELEMS ((size_t)B * S * H)

// ---------------------------------------------------------------------------
// Device scratch (allocation-free)
// ---------------------------------------------------------------------------
__device__ float g_q[B * S * H];
__device__ float g_k[B * S * H];
__device__ float g_v[B * S * H];

__device__ __nv_bfloat16 g_ah[(size_t)GM * GK];
__device__ __nv_bfloat16 g_al[(size_t)GM * GK];
__device__ __nv_bfloat16 g_wh[3][(size_t)GN * GK];
__device__ __nv_bfloat16 g_wl[3][(size_t)GN * GK];

// ---------------------------------------------------------------------------
// Helpers
// ---------------------------------------------------------------------------
__device__ __forceinline__ uint32_t smem_u32(const void* p) {
    uint32_t a;
    asm("{ .reg .u64 t; cvta.to.shared.u64 t, %1; cvt.u32.u64 %0, t; }"
        : "=r"(a) : "l"(p));
    return a;
}

__device__ __forceinline__ void cp16(uint32_t dst, const void* src) {
    asm volatile("cp.async.cg.shared.global [%0], [%1], 16;"
                 :: "r"(dst), "l"(src));
}
#define CP_COMMIT() asm volatile("cp.async.commit_group;" ::: "memory")
#define CP_WAIT1()  asm volatile("cp.async.wait_group 1;" ::: "memory")

__device__ __forceinline__ void ldsm4(uint32_t* r, uint32_t addr) {
    asm volatile("ldmatrix.sync.aligned.m8n8.x4.shared.b16 {%0,%1,%2,%3}, [%4];"
                 : "=r"(r[0]), "=r"(r[1]), "=r"(r[2]), "=r"(r[3]) : "r"(addr));
}

__device__ __forceinline__ void mma16816(float* c, const uint32_t* a,
                                         uint32_t b0, uint32_t b1) {
    asm volatile(
        "mma.sync.aligned.m16n8k16.row.col.f32.bf16.bf16.f32 "
        "{%0,%1,%2,%3}, {%4,%5,%6,%7}, {%8,%9}, {%0,%1,%2,%3};"
        : "+f"(c[0]), "+f"(c[1]), "+f"(c[2]), "+f"(c[3])
        : "r"(a[0]), "r"(a[1]), "r"(a[2]), "r"(a[3]), "r"(b0), "r"(b1));
}

// ---------------------------------------------------------------------------
// Split fp32 -> bf16 (hi, lo)
// ---------------------------------------------------------------------------
__global__ __launch_bounds__(256) void split_bf16(
    const float* __restrict__ x,
    __nv_bfloat16* __restrict__ hi, __nv_bfloat16* __restrict__ lo, int n8)
{
    int i = blockIdx.x * blockDim.x + threadIdx.x;
    if (i >= n8) return;
    const float4* xp = (const float4*)x + (size_t)i * 2;
    float4 a = xp[0], b = xp[1];
    float f[8] = {a.x, a.y, a.z, a.w, b.x, b.y, b.z, b.w};
    __align__(16) __nv_bfloat16 h[8];
    __align__(16) __nv_bfloat16 l[8];
    #pragma unroll
    for (int j = 0; j < 8; j++) {
        h[j] = __float2bfloat16(f[j]);
        l[j] = __float2bfloat16(f[j] - __bfloat162float(h[j]));
    }
    *(uint4*)(hi + (size_t)i * 8) = *(uint4*)h;
    *(uint4*)(lo + (size_t)i * 8) = *(uint4*)l;
}

// ---------------------------------------------------------------------------
// QKV GEMM via mma.sync (HMMA bf16, fp32 accum), 3-term split.
// C = A @ W^T + bias.  Block tile 128x128, K-chunk 64, double-buffered cp.async.
// 8 warps: warp tile 32(M) x 64(N).
// ---------------------------------------------------------------------------
#define TM 128
#define TN 128
#define TK 64
#define NCHUNK (GK / TK)              // 16
#define TILE_B  (TM * TK * 2)         // 16384 bytes per tile (128 rows x 128B)
#define STAGE_B (4 * TILE_B)          // Ah, Al, Bh, Bl
#define GSMEM   (2 * STAGE_B + 1024)

__global__ __launch_bounds__(256, 1) void qkv_gemm_mma(
    const float* __restrict__ bias_q,
    const float* __restrict__ bias_k,
    const float* __restrict__ bias_v)
{
    extern __shared__ char dsm_raw[];
    char* sb = (char*)(((uintptr_t)dsm_raw + 1023) & ~(uintptr_t)1023);

    const int z  = blockIdx.z;
    const int bm = blockIdx.y * TM;
    const int bn = blockIdx.x * TN;

    const __nv_bfloat16* Ah = g_ah;
    const __nv_bfloat16* Al = g_al;
    const __nv_bfloat16* Bh = g_wh[z];
    const __nv_bfloat16* Bl = g_wl[z];
    const float* bias = (z == 0) ? bias_q : (z == 1) ? bias_k : bias_v;
    float* Cout = (z == 0) ? g_q : (z == 1) ? g_k : g_v;

    const int tid  = threadIdx.x;
    const int wid  = tid >> 5;
    const int lane = tid & 31;
    const int wm   = (wid >> 1) * 32;   // 0,32,64,96
    const int wn   = (wid & 1) * 64;    // 0,64

    const uint32_t sbase = smem_u32(sb);

    // ---- loader lambda: chunk c into stage buffer `buf` ----
    // per thread: 4 iterations per tile x 4 tiles = 16 cp.async of 16B
    auto load_chunk = [&](int c, int buf) {
        const int kc = c * TK;
        const uint32_t stage = sbase + buf * STAGE_B;
        #pragma unroll
        for (int t = 0; t < 4; t++) {
            const __nv_bfloat16* src;
            int rbase;
            switch (t) {
                case 0: src = Ah; rbase = bm; break;
                case 1: src = Al; rbase = bm; break;
                case 2: src = Bh; rbase = bn; break;
                default: src = Bl; rbase = bn; break;
            }
            uint32_t dtile = stage + t * TILE_B;
            #pragma unroll
            for (int i = 0; i < 4; i++) {
                int idx = tid + i * 256;       // 0..1023
                int row = idx >> 3;            // 0..127
                int v   = idx & 7;             // 16B slot
                uint32_t off = (uint32_t)(row << 7) + (uint32_t)(v << 4);
                off ^= (off >> 3) & 0x70;
                cp16(dtile + off, src + (size_t)(rbase + row) * GK + kc + v * 8);
            }
        }
    };

    float acc[2][8][4];
    #pragma unroll
    for (int f = 0; f < 2; f++)
        #pragma unroll
        for (int g = 0; g < 8; g++)
            #pragma unroll
            for (int j = 0; j < 4; j++) acc[f][g][j] = 0.f;

    // Precompute per-lane ldmatrix row/col pieces
    const int a_row_l = lane & 15;                       // within m16
    const int a_kb_l  = (lane >> 4) << 4;                // 0 or 16
    const int b_row_l = (lane & 7) + ((lane >> 4) << 3); // within n16
    const int b_kb_l  = ((lane >> 3) & 1) << 4;          // 0 or 16

    load_chunk(0, 0); CP_COMMIT();
    load_chunk(1, 1); CP_COMMIT();

    for (int c = 0; c < NCHUNK; c++) {
        const int buf = c & 1;
        CP_WAIT1();
        __syncthreads();

        const uint32_t stage  = sbase + buf * STAGE_B;
        const uint32_t baseAh = stage;
        const uint32_t baseAl = stage + TILE_B;
        const uint32_t baseBh = stage + 2 * TILE_B;
        const uint32_t baseBl = stage + 3 * TILE_B;

        #pragma unroll
        for (int s = 0; s < 4; s++) {
            uint32_t aH[2][4], aL[2][4], bH[4][4], bL[4][4];
            #pragma unroll
            for (int f = 0; f < 2; f++) {
                int row = wm + f * 16 + a_row_l;
                int cb  = s * 32 + a_kb_l;
                uint32_t off = (uint32_t)(row << 7) + (uint32_t)(cb ^ ((row & 7) << 4));
                ldsm4(aH[f], baseAh + off);
                ldsm4(aL[f], baseAl + off);
            }
            #pragma unroll
            for (int g16 = 0; g16 < 4; g16++) {
                int row = wn + g16 * 16 + b_row_l;
                int cb  = s * 32 + b_kb_l;
                uint32_t off = (uint32_t)(row << 7) + (uint32_t)(cb ^ ((row & 7) << 4));
                ldsm4(bH[g16], baseBh + off);
                ldsm4(bL[g16], baseBl + off);
            }
            #pragma unroll
            for (int f = 0; f < 2; f++) {
                #pragma unroll
                for (int g16 = 0; g16 < 4; g16++) {
                    #pragma unroll
                    for (int p = 0; p < 2; p++) {
                        float* cc = acc[f][g16 * 2 + p];
                        mma16816(cc, aH[f], bH[g16][2*p], bH[g16][2*p+1]);
                        mma16816(cc, aH[f], bL[g16][2*p], bL[g16][2*p+1]);
                        mma16816(cc, aL[f], bH[g16][2*p], bH[g16][2*p+1]);
                    }
                }
            }
        }
        __syncthreads();
        if (c + 2 < NCHUNK) load_chunk(c + 2, buf);
        CP_COMMIT();
    }

    // ---- epilogue: bias + store fp32 ----
    #pragma unroll
    for (int f = 0; f < 2; f++) {
        #pragma unroll
        for (int g = 0; g < 8; g++) {
            int row = bm + wm + f * 16 + (lane >> 2);
            int col = bn + wn + g * 8 + (lane & 3) * 2;
            float b0 = bias[col], b1 = bias[col + 1];
            float2 o0 = make_float2(acc[f][g][0] + b0, acc[f][g][1] + b1);
            float2 o1 = make_float2(acc[f][g][2] + b0, acc[f][g][3] + b1);
            *(float2*)(Cout + (size_t)row * GN + col)       = o0;
            *(float2*)(Cout + (size_t)(row + 8) * GN + col) = o1;
        }
    }
}

// ---------------------------------------------------------------------------
// Global attention: one block per (b,h)
// ---------------------------------------------------------------------------
__global__ __launch_bounds__(1024) void global_attn(
    const float* __restrict__ mask, float* __restrict__ out)
{
    const int bh = blockIdx.x;
    const int b  = bh / NH;
    const int h  = bh % NH;

    __shared__ float sq[D];
    __shared__ float scores[S];
    __shared__ float red[32];
    __shared__ float pacc[32][65];

    const int tid  = threadIdx.x;
    const int lane = tid & 31;
    const int w    = tid >> 5;

    const float* qbase = g_q + ((size_t)b * S + 0) * H + h * D;
    if (tid < D) sq[tid] = qbase[tid];
    __syncthreads();

    for (int s = tid; s < S; s += 1024) {
        const float4* krow = (const float4*)(g_k + ((size_t)b * S + s) * H + h * D);
        float acc = 0.f;
        #pragma unroll
        for (int i = 0; i < 16; i++) {
            float4 kv = krow[i];
            acc = fmaf(kv.x, sq[4*i+0], acc);
            acc = fmaf(kv.y, sq[4*i+1], acc);
            acc = fmaf(kv.z, sq[4*i+2], acc);
            acc = fmaf(kv.w, sq[4*i+3], acc);
        }
        scores[s] = acc * SCALE + mask[(size_t)b * S + s];
    }
    __syncthreads();

    float lm = -INFINITY;
    for (int s = tid; s < S; s += 1024) lm = fmaxf(lm, scores[s]);
    #pragma unroll
    for (int o = 16; o; o >>= 1) lm = fmaxf(lm, __shfl_xor_sync(~0u, lm, o));
    if (lane == 0) red[w] = lm;
    __syncthreads();
    if (w == 0) {
        float v = red[lane];
        #pragma unroll
        for (int o = 16; o; o >>= 1) v = fmaxf(v, __shfl_xor_sync(~0u, v, o));
        if (lane == 0) red[0] = v;
    }
    __syncthreads();
    const float m = red[0];
    __syncthreads();

    float ls = 0.f;
    for (int s = tid; s < S; s += 1024) {
        float p = expf(scores[s] - m);
        scores[s] = p;
        ls += p;
    }
    #pragma unroll
    for (int o = 16; o; o >>= 1) ls += __shfl_xor_sync(~0u, ls, o);
    if (lane == 0) red[w] = ls;
    __syncthreads();
    if (w == 0) {
        float v = red[lane];
        #pragma unroll
        for (int o = 16; o; o >>= 1) v += __shfl_xor_sync(~0u, v, o);
        if (lane == 0) red[0] = v;
    }
    __syncthreads();
    const float denom = red[0];

    float acc0 = 0.f, acc1 = 0.f;
    const int s0 = w * (S / 32);
    for (int i = 0; i < S / 32; i++) {
        int s = s0 + i;
        float p = scores[s];
        float2 v2 = ((const float2*)(g_v + ((size_t)b * S + s) * H + h * D))[lane];
        acc0 = fmaf(p, v2.x, acc0);
        acc1 = fmaf(p, v2.y, acc1);
    }
    pacc[w][2*lane]   = acc0;
    pacc[w][2*lane+1] = acc1;
    __syncthreads();

    if (tid < D) {
        float sum = 0.f;
        #pragma unroll
        for (int ww = 0; ww < 32; ww++) sum += pacc[ww][tid];
        out[((size_t)b * S + 0) * H + h * D + tid] = sum / denom;
    }
}

// ---------------------------------------------------------------------------
// Local attention: one warp per (b, h, s), s in 1..S-1
// ---------------------------------------------------------------------------
__global__ __launch_bounds__(256) void local_attn(float* __restrict__ out)
{
    const int gwarp = (blockIdx.x * blockDim.x + threadIdx.x) >> 5;
    const int lane  = threadIdx.x & 31;
    const int total = B * NH * (S - 1);
    if (gwarp >= total) return;

    const int s1 = gwarp % (S - 1);
    const int s  = s1 + 1;
    const int bh = gwarp / (S - 1);
    const int h  = bh % NH;
    const int b  = bh / NH;

    const size_t base_s = ((size_t)b * S + s) * H + (size_t)h * D;
    const size_t base_0 = ((size_t)b * S + 0) * H + (size_t)h * D;

    float2 q2 = ((const float2*)(g_q + base_s))[lane];
    float2 k2 = ((const float2*)(g_k + base_s))[lane];
    float2 k0 = ((const float2*)(g_k + base_0))[lane];

    float ps = q2.x * k2.x + q2.y * k2.y;
    float pg = q2.x * k0.x + q2.y * k0.y;
    #pragma unroll
    for (int o = 16; o; o >>= 1) {
        ps += __shfl_xor_sync(~0u, ps, o);
        pg += __shfl_xor_sync(~0u, pg, o);
    }
    ps *= SCALE;
    pg *= SCALE;

    float m  = fmaxf(ps, pg);
    float e0 = expf(ps - m);
    float e1 = expf(pg - m);
    float inv = 1.f / (e0 + e1);
    float p0 = e0 * inv;
    float p1 = e1 * inv;

    float2 v2 = ((const float2*)(g_v + base_s))[lane];
    float2 v0 = ((const float2*)(g_v + base_0))[lane];
    float2 o2;
    o2.x = p0 * v2.x + p1 * v0.x;
    o2.y = p0 * v2.y + p1 * v0.y;
    ((float2*)(out + base_s))[lane] = o2;

    if (lane == 0) {
        size_t li = CTX_ELEMS + ((size_t)bh * (S - 1) + s1) * 2;
        out[li]     = p0;
        out[li + 1] = p1;
    }
}

// ---------------------------------------------------------------------------
extern "C" void kernel_launch(void* const* d_in, const int* in_sizes, int n_in,
                              void* d_out, int out_size)
{
    const float* hidden = (const float*)d_in[0];
    const float* mask   = (const float*)d_in[1];
    const float* Wq     = (const float*)d_in[2];
    const float* bq     = (const float*)d_in[3];
    const float* Wk     = (const float*)d_in[4];
    const float* bk     = (const float*)d_in[5];
    const float* Wv     = (const float*)d_in[6];
    const float* bv     = (const float*)d_in[7];
    float* out = (float*)d_out;

    __nv_bfloat16 *ah, *al, *wh, *wl;
    cudaGetSymbolAddress((void**)&ah, g_ah);
    cudaGetSymbolAddress((void**)&al, g_al);
    cudaGetSymbolAddress((void**)&wh, g_wh);
    cudaGetSymbolAddress((void**)&wl, g_wl);

    {
        int n8 = (GM * GK) / 8;
        split_bf16<<<n8 / 256, 256>>>(hidden, ah, al, n8);
        int w8 = (GN * GK) / 8;
        split_bf16<<<w8 / 256, 256>>>(Wq, wh + 0 * (size_t)GN * GK, wl + 0 * (size_t)GN * GK, w8);
        split_bf16<<<w8 / 256, 256>>>(Wk, wh + 1 * (size_t)GN * GK, wl + 1 * (size_t)GN * GK, w8);
        split_bf16<<<w8 / 256, 256>>>(Wv, wh + 2 * (size_t)GN * GK, wl + 2 * (size_t)GN * GK, w8);
    }

    static bool attr_set = false;
    if (!attr_set) {
        cudaFuncSetAttribute(qkv_gemm_mma, cudaFuncAttributeMaxDynamicSharedMemorySize, GSMEM);
        attr_set = true;
    }
    dim3 ggrid(GN / TN, GM / TM, 3);   // (8, 128, 3)
    qkv_gemm_mma<<<ggrid, 256, GSMEM>>>(bq, bk, bv);

    global_attn<<<B * NH, 1024>>>(mask, out);

    const int totalWarps = B * NH * (S - 1);
    const int blocks = (totalWarps * 32 + 255) / 256;
    local_attn<<<blocks, 256>>>(out);
}

// round 4
// speedup vs baseline: 3.0974x; 1.0125x over previous
#include <cuda_runtime.h>
#include <cuda_bf16.h>
#include <math.h>
#include <cstdint>

// ---------------------------------------------------------------------------
// Problem constants
// ---------------------------------------------------------------------------
#define B  4
#define S  4096
#define H  1024
#define NH 16
#define D  64
#define SCALE 0.125f

#define GM (B*S)   // 16384
#define GN H       // 1024
#define GK H       // 1024

#define CTX_ELEMS ((size_t)B * S * H)

// ---------------------------------------------------------------------------
// Device scratch (allocation-free)
// ---------------------------------------------------------------------------
__device__ float g_q[B * S * H];
__device__ float g_k[B * S * H];
__device__ float g_v[B * S * H];

__device__ __nv_bfloat16 g_ah[(size_t)GM * GK];
__device__ __nv_bfloat16 g_al[(size_t)GM * GK];
__device__ __nv_bfloat16 g_wh[3][(size_t)GN * GK];
__device__ __nv_bfloat16 g_wl[3][(size_t)GN * GK];

// global-attention partials: 64 bh x 8 chunks
#define GCH 8
__device__ float g_pmax[B * NH][GCH];
__device__ float g_psum[B * NH][GCH];
__device__ float g_pvac[B * NH][GCH][D];

// ---------------------------------------------------------------------------
// Helpers
// ---------------------------------------------------------------------------
__device__ __forceinline__ uint32_t smem_u32(const void* p) {
    uint32_t a;
    asm("{ .reg .u64 t; cvta.to.shared.u64 t, %1; cvt.u32.u64 %0, t; }"
        : "=r"(a) : "l"(p));
    return a;
}

__device__ __forceinline__ void cp16(uint32_t dst, const void* src) {
    asm volatile("cp.async.cg.shared.global [%0], [%1], 16;"
                 :: "r"(dst), "l"(src));
}
#define CP_COMMIT() asm volatile("cp.async.commit_group;" ::: "memory")
#define CP_WAIT2()  asm volatile("cp.async.wait_group 2;" ::: "memory")

__device__ __forceinline__ void ldsm4(uint32_t* r, uint32_t addr) {
    asm volatile("ldmatrix.sync.aligned.m8n8.x4.shared.b16 {%0,%1,%2,%3}, [%4];"
                 : "=r"(r[0]), "=r"(r[1]), "=r"(r[2]), "=r"(r[3]) : "r"(addr));
}

__device__ __forceinline__ void mma16816(float* c, const uint32_t* a,
                                         uint32_t b0, uint32_t b1) {
    asm volatile(
        "mma.sync.aligned.m16n8k16.row.col.f32.bf16.bf16.f32 "
        "{%0,%1,%2,%3}, {%4,%5,%6,%7}, {%8,%9}, {%0,%1,%2,%3};"
        : "+f"(c[0]), "+f"(c[1]), "+f"(c[2]), "+f"(c[3])
        : "r"(a[0]), "r"(a[1]), "r"(a[2]), "r"(a[3]), "r"(b0), "r"(b1));
}

// ---------------------------------------------------------------------------
// Unified split: hidden + Wq + Wk + Wv  ->  bf16 hi/lo, one launch.
// Each index i handles 8 floats.
// ---------------------------------------------------------------------------
#define HN8 ((GM * GK) / 8)    // 2,097,152
#define WN8 ((GN * GK) / 8)    // 131,072
#define TOTN8 (HN8 + 3 * WN8)  // 2,490,368

__global__ __launch_bounds__(256) void split_all(
    const float* __restrict__ hidden,
    const float* __restrict__ Wq,
    const float* __restrict__ Wk,
    const float* __restrict__ Wv)
{
    int i = blockIdx.x * blockDim.x + threadIdx.x;
    if (i >= TOTN8) return;

    const float* src;
    __nv_bfloat16 *hi, *lo;
    size_t off;
    if (i < HN8) {
        src = hidden; hi = g_ah; lo = g_al; off = (size_t)i * 8;
    } else {
        int j = i - HN8;
        int w = j / WN8;
        off = (size_t)(j - w * WN8) * 8;
        src = (w == 0) ? Wq : (w == 1) ? Wk : Wv;
        hi = g_wh[w]; lo = g_wl[w];
    }

    const float4* xp = (const float4*)(src + off);
    float4 a = xp[0], b = xp[1];
    float f[8] = {a.x, a.y, a.z, a.w, b.x, b.y, b.z, b.w};
    __align__(16) __nv_bfloat16 h[8];
    __align__(16) __nv_bfloat16 l[8];
    #pragma unroll
    for (int j = 0; j < 8; j++) {
        h[j] = __float2bfloat16(f[j]);
        l[j] = __float2bfloat16(f[j] - __bfloat162float(h[j]));
    }
    *(uint4*)(hi + off) = *(uint4*)h;
    *(uint4*)(lo + off) = *(uint4*)l;
}

// ---------------------------------------------------------------------------
// QKV GEMM via mma.sync (HMMA bf16, fp32 accum), 3-term split.
// Block tile 128x128, K-chunk 64, 3-stage cp.async pipeline.
// ---------------------------------------------------------------------------
#define TM 128
#define TN 128
#define TK 64
#define NCHUNK (GK / TK)              // 16
#define TILE_B  (TM * TK * 2)         // 16384 bytes
#define STAGE_B (4 * TILE_B)          // 64 KB: Ah, Al, Bh, Bl
#define NSTAGE  3
#define GSMEM   (NSTAGE * STAGE_B + 1024)

__global__ __launch_bounds__(256, 1) void qkv_gemm_mma(
    const float* __restrict__ bias_q,
    const float* __restrict__ bias_k,
    const float* __restrict__ bias_v)
{
    extern __shared__ char dsm_raw[];
    char* sb = (char*)(((uintptr_t)dsm_raw + 1023) & ~(uintptr_t)1023);

    const int z  = blockIdx.z;
    const int bm = blockIdx.y * TM;
    const int bn = blockIdx.x * TN;

    const __nv_bfloat16* Ah = g_ah;
    const __nv_bfloat16* Al = g_al;
    const __nv_bfloat16* Bh = g_wh[z];
    const __nv_bfloat16* Bl = g_wl[z];
    const float* bias = (z == 0) ? bias_q : (z == 1) ? bias_k : bias_v;
    float* Cout = (z == 0) ? g_q : (z == 1) ? g_k : g_v;

    const int tid  = threadIdx.x;
    const int wid  = tid >> 5;
    const int lane = tid & 31;
    const int wm   = (wid >> 1) * 32;   // 0,32,64,96
    const int wn   = (wid & 1) * 64;    // 0,64

    const uint32_t sbase = smem_u32(sb);

    auto load_chunk = [&](int c, int buf) {
        const int kc = c * TK;
        const uint32_t stage = sbase + buf * STAGE_B;
        #pragma unroll
        for (int t = 0; t < 4; t++) {
            const __nv_bfloat16* src;
            int rbase;
            switch (t) {
                case 0: src = Ah; rbase = bm; break;
                case 1: src = Al; rbase = bm; break;
                case 2: src = Bh; rbase = bn; break;
                default: src = Bl; rbase = bn; break;
            }
            uint32_t dtile = stage + t * TILE_B;
            #pragma unroll
            for (int i = 0; i < 4; i++) {
                int idx = tid + i * 256;
                int row = idx >> 3;
                int v   = idx & 7;
                uint32_t off = (uint32_t)(row << 7) + (uint32_t)(v << 4);
                off ^= (off >> 3) & 0x70;
                cp16(dtile + off, src + (size_t)(rbase + row) * GK + kc + v * 8);
            }
        }
    };

    float acc[2][8][4];
    #pragma unroll
    for (int f = 0; f < 2; f++)
        #pragma unroll
        for (int g = 0; g < 8; g++)
            #pragma unroll
            for (int j = 0; j < 4; j++) acc[f][g][j] = 0.f;

    const int a_row_l = lane & 15;
    const int a_kb_l  = (lane >> 4) << 4;
    const int b_row_l = (lane & 7) + ((lane >> 4) << 3);
    const int b_kb_l  = ((lane >> 3) & 1) << 4;

    load_chunk(0, 0); CP_COMMIT();
    load_chunk(1, 1); CP_COMMIT();

    for (int c = 0; c < NCHUNK; c++) {
        const int buf = c % NSTAGE;
        // prefetch chunk c+2 into its stage (safe: stage (c+2)%3 was computed
        // at iteration c-1, and a trailing __syncthreads protects it)
        if (c + 2 < NCHUNK) load_chunk(c + 2, (c + 2) % NSTAGE);
        CP_COMMIT();
        CP_WAIT2();          // chunk c complete
        __syncthreads();

        const uint32_t stage  = sbase + buf * STAGE_B;
        const uint32_t baseAh = stage;
        const uint32_t baseAl = stage + TILE_B;
        const uint32_t baseBh = stage + 2 * TILE_B;
        const uint32_t baseBl = stage + 3 * TILE_B;

        #pragma unroll
        for (int s = 0; s < 4; s++) {
            uint32_t aH[2][4], aL[2][4], bH[4][4], bL[4][4];
            #pragma unroll
            for (int f = 0; f < 2; f++) {
                int row = wm + f * 16 + a_row_l;
                int cb  = s * 32 + a_kb_l;
                uint32_t off = (uint32_t)(row << 7) + (uint32_t)(cb ^ ((row & 7) << 4));
                ldsm4(aH[f], baseAh + off);
                ldsm4(aL[f], baseAl + off);
            }
            #pragma unroll
            for (int g16 = 0; g16 < 4; g16++) {
                int row = wn + g16 * 16 + b_row_l;
                int cb  = s * 32 + b_kb_l;
                uint32_t off = (uint32_t)(row << 7) + (uint32_t)(cb ^ ((row & 7) << 4));
                ldsm4(bH[g16], baseBh + off);
                ldsm4(bL[g16], baseBl + off);
            }
            #pragma unroll
            for (int f = 0; f < 2; f++) {
                #pragma unroll
                for (int g16 = 0; g16 < 4; g16++) {
                    #pragma unroll
                    for (int p = 0; p < 2; p++) {
                        float* cc = acc[f][g16 * 2 + p];
                        mma16816(cc, aH[f], bH[g16][2*p], bH[g16][2*p+1]);
                        mma16816(cc, aH[f], bL[g16][2*p], bL[g16][2*p+1]);
                        mma16816(cc, aL[f], bH[g16][2*p], bH[g16][2*p+1]);
                    }
                }
            }
        }
        __syncthreads();
    }

    // ---- epilogue ----
    #pragma unroll
    for (int f = 0; f < 2; f++) {
        #pragma unroll
        for (int g = 0; g < 8; g++) {
            int row = bm + wm + f * 16 + (lane >> 2);
            int col = bn + wn + g * 8 + (lane & 3) * 2;
            float b0 = bias[col], b1 = bias[col + 1];
            float2 o0 = make_float2(acc[f][g][0] + b0, acc[f][g][1] + b1);
            float2 o1 = make_float2(acc[f][g][2] + b0, acc[f][g][3] + b1);
            *(float2*)(Cout + (size_t)row * GN + col)       = o0;
            *(float2*)(Cout + (size_t)(row + 8) * GN + col) = o1;
        }
    }
}

// ---------------------------------------------------------------------------
// Global attention pass 1: grid (GCH, 64). Each block: 512 keys of one (b,h).
// Produces partial (max, sum, vacc[64]).
// ---------------------------------------------------------------------------
#define SCHUNK (S / GCH)   // 512

__global__ __launch_bounds__(256) void gattn_part(const float* __restrict__ mask)
{
    const int ch = blockIdx.x;
    const int bh = blockIdx.y;
    const int b  = bh / NH;
    const int h  = bh % NH;

    __shared__ float sq[D];
    __shared__ float sp[SCHUNK];
    __shared__ float red[8];
    __shared__ float vwarp[8][D];

    const int tid  = threadIdx.x;
    const int lane = tid & 31;
    const int w    = tid >> 5;

    if (tid < D) sq[tid] = g_q[((size_t)b * S) * H + h * D + tid];
    __syncthreads();

    const float q0 = sq[2 * lane];
    const float q1 = sq[2 * lane + 1];
    const int sbase = ch * SCHUNK + w * (SCHUNK / 8);   // 64 rows per warp

    // scores
    for (int i = 0; i < SCHUNK / 8; i++) {
        int s = sbase + i;
        float2 k2 = ((const float2*)(g_k + ((size_t)b * S + s) * H + h * D))[lane];
        float ps = q0 * k2.x + q1 * k2.y;
        #pragma unroll
        for (int o = 16; o; o >>= 1) ps += __shfl_xor_sync(~0u, ps, o);
        if (lane == 0)
            sp[w * (SCHUNK / 8) + i] = ps * SCALE + mask[(size_t)b * S + s];
    }
    __syncthreads();

    // block max over 512 scores
    float lm = fmaxf(sp[tid], sp[tid + 256]);
    #pragma unroll
    for (int o = 16; o; o >>= 1) lm = fmaxf(lm, __shfl_xor_sync(~0u, lm, o));
    if (lane == 0) red[w] = lm;
    __syncthreads();
    float bm = red[0];
    #pragma unroll
    for (int ww = 1; ww < 8; ww++) bm = fmaxf(bm, red[ww]);
    __syncthreads();

    // exp + sum
    float e0 = expf(sp[tid] - bm);
    float e1 = expf(sp[tid + 256] - bm);
    sp[tid] = e0; sp[tid + 256] = e1;
    float ls = e0 + e1;
    #pragma unroll
    for (int o = 16; o; o >>= 1) ls += __shfl_xor_sync(~0u, ls, o);
    if (lane == 0) red[w] = ls;
    __syncthreads();
    float bsum = 0.f;
    #pragma unroll
    for (int ww = 0; ww < 8; ww++) bsum += red[ww];

    // weighted V partial (each warp: its 64 rows, lane holds dims 2l,2l+1)
    float a0 = 0.f, a1 = 0.f;
    for (int i = 0; i < SCHUNK / 8; i++) {
        int s = sbase + i;
        float p = sp[w * (SCHUNK / 8) + i];
        float2 v2 = ((const float2*)(g_v + ((size_t)b * S + s) * H + h * D))[lane];
        a0 = fmaf(p, v2.x, a0);
        a1 = fmaf(p, v2.y, a1);
    }
    vwarp[w][2 * lane]     = a0;
    vwarp[w][2 * lane + 1] = a1;
    __syncthreads();

    if (tid < D) {
        float vs = 0.f;
        #pragma unroll
        for (int ww = 0; ww < 8; ww++) vs += vwarp[ww][tid];
        g_pvac[bh][ch][tid] = vs;
    }
    if (tid == 0) {
        g_pmax[bh][ch] = bm;
        g_psum[bh][ch] = bsum;
    }
}

// pass 2: combine partials. 64 blocks x 64 threads.
__global__ __launch_bounds__(64) void gattn_combine(float* __restrict__ out)
{
    const int bh = blockIdx.x;
    const int b  = bh / NH;
    const int h  = bh % NH;
    const int tid = threadIdx.x;

    float M = -INFINITY;
    #pragma unroll
    for (int c = 0; c < GCH; c++) M = fmaxf(M, g_pmax[bh][c]);
    float denom = 0.f, vs = 0.f;
    #pragma unroll
    for (int c = 0; c < GCH; c++) {
        float sc = expf(g_pmax[bh][c] - M);
        denom += g_psum[bh][c] * sc;
        vs    += g_pvac[bh][c][tid] * sc;
    }
    out[((size_t)b * S) * H + h * D + tid] = vs / denom;
}

// ---------------------------------------------------------------------------
// Local attention: one warp per (b, h, s), s in 1..S-1
// ---------------------------------------------------------------------------
__global__ __launch_bounds__(256) void local_attn(float* __restrict__ out)
{
    const int gwarp = (blockIdx.x * blockDim.x + threadIdx.x) >> 5;
    const int lane  = threadIdx.x & 31;
    const int total = B * NH * (S - 1);
    if (gwarp >= total) return;

    const int s1 = gwarp % (S - 1);
    const int s  = s1 + 1;
    const int bh = gwarp / (S - 1);
    const int h  = bh % NH;
    const int b  = bh / NH;

    const size_t base_s = ((size_t)b * S + s) * H + (size_t)h * D;
    const size_t base_0 = ((size_t)b * S + 0) * H + (size_t)h * D;

    float2 q2 = ((const float2*)(g_q + base_s))[lane];
    float2 k2 = ((const float2*)(g_k + base_s))[lane];
    float2 k0 = ((const float2*)(g_k + base_0))[lane];

    float ps = q2.x * k2.x + q2.y * k2.y;
    float pg = q2.x * k0.x + q2.y * k0.y;
    #pragma unroll
    for (int o = 16; o; o >>= 1) {
        ps += __shfl_xor_sync(~0u, ps, o);
        pg += __shfl_xor_sync(~0u, pg, o);
    }
    ps *= SCALE;
    pg *= SCALE;

    float m  = fmaxf(ps, pg);
    float e0 = expf(ps - m);
    float e1 = expf(pg - m);
    float inv = 1.f / (e0 + e1);
    float p0 = e0 * inv;
    float p1 = e1 * inv;

    float2 v2 = ((const float2*)(g_v + base_s))[lane];
    float2 v0 = ((const float2*)(g_v + base_0))[lane];
    float2 o2;
    o2.x = p0 * v2.x + p1 * v0.x;
    o2.y = p0 * v2.y + p1 * v0.y;
    ((float2*)(out + base_s))[lane] = o2;

    if (lane == 0) {
        size_t li = CTX_ELEMS + ((size_t)bh * (S - 1) + s1) * 2;
        out[li]     = p0;
        out[li + 1] = p1;
    }
}

// ---------------------------------------------------------------------------
extern "C" void kernel_launch(void* const* d_in, const int* in_sizes, int n_in,
                              void* d_out, int out_size)
{
    const float* hidden = (const float*)d_in[0];
    const float* mask   = (const float*)d_in[1];
    const float* Wq     = (const float*)d_in[2];
    const float* bq     = (const float*)d_in[3];
    const float* Wk     = (const float*)d_in[4];
    const float* bk     = (const float*)d_in[5];
    const float* Wv     = (const float*)d_in[6];
    const float* bv     = (const float*)d_in[7];
    float* out = (float*)d_out;

    split_all<<<(TOTN8 + 255) / 256, 256>>>(hidden, Wq, Wk, Wv);

    static bool attr_set = false;
    if (!attr_set) {
        cudaFuncSetAttribute(qkv_gemm_mma, cudaFuncAttributeMaxDynamicSharedMemorySize, GSMEM);
        attr_set = true;
    }
    dim3 ggrid(GN / TN, GM / TM, 3);
    qkv_gemm_mma<<<ggrid, 256, GSMEM>>>(bq, bk, bv);

    dim3 pgrid(GCH, B * NH);
    gattn_part<<<pgrid, 256>>>(mask);
    gattn_combine<<<B * NH, 64>>>(out);

    const int totalWarps = B * NH * (S - 1);
    const int blocks = (totalWarps * 32 + 255) / 256;
    local_attn<<<blocks, 256>>>(out);
}

// round 5
// speedup vs baseline: 3.2239x; 1.0408x over previous
#include <cuda_runtime.h>
#include <cuda_bf16.h>
#include <math.h>
#include <cstdint>

// ---------------------------------------------------------------------------
// Problem constants
// ---------------------------------------------------------------------------
#define B  4
#define S  4096
#define H  1024
#define NH 16
#define D  64
#define SCALE 0.125f

#define GM (B*S)   // 16384
#define GN H       // 1024
#define GK H       // 1024

#define CTX_ELEMS ((size_t)B * S * H)

// ---------------------------------------------------------------------------
// Device scratch (allocation-free)
// ---------------------------------------------------------------------------
__device__ float g_q[B * S * H];
__device__ float g_k[B * S * H];
__device__ float g_v[B * S * H];

__device__ __nv_bfloat16 g_ah[(size_t)GM * GK];
__device__ __nv_bfloat16 g_al[(size_t)GM * GK];
__device__ __nv_bfloat16 g_wh[3][(size_t)GN * GK];
__device__ __nv_bfloat16 g_wl[3][(size_t)GN * GK];

#define GCH 8
__device__ float g_pmax[B * NH][GCH];
__device__ float g_psum[B * NH][GCH];
__device__ float g_pvac[B * NH][GCH][D];

// ---------------------------------------------------------------------------
// Helpers
// ---------------------------------------------------------------------------
__device__ __forceinline__ uint32_t smem_u32(const void* p) {
    uint32_t a;
    asm("{ .reg .u64 t; cvta.to.shared.u64 t, %1; cvt.u32.u64 %0, t; }"
        : "=r"(a) : "l"(p));
    return a;
}

__device__ __forceinline__ void cp16(uint32_t dst, const void* src) {
    asm volatile("cp.async.cg.shared.global [%0], [%1], 16;"
                 :: "r"(dst), "l"(src));
}
#define CP_COMMIT() asm volatile("cp.async.commit_group;" ::: "memory")
#define CP_WAIT0()  asm volatile("cp.async.wait_group 0;" ::: "memory")
#define CP_WAIT1()  asm volatile("cp.async.wait_group 1;" ::: "memory")

__device__ __forceinline__ void ldsm4(uint32_t* r, uint32_t addr) {
    asm volatile("ldmatrix.sync.aligned.m8n8.x4.shared.b16 {%0,%1,%2,%3}, [%4];"
                 : "=r"(r[0]), "=r"(r[1]), "=r"(r[2]), "=r"(r[3]) : "r"(addr));
}

__device__ __forceinline__ void mma16816(float* c, const uint32_t* a,
                                         uint32_t b0, uint32_t b1) {
    asm volatile(
        "mma.sync.aligned.m16n8k16.row.col.f32.bf16.bf16.f32 "
        "{%0,%1,%2,%3}, {%4,%5,%6,%7}, {%8,%9}, {%0,%1,%2,%3};"
        : "+f"(c[0]), "+f"(c[1]), "+f"(c[2]), "+f"(c[3])
        : "r"(a[0]), "r"(a[1]), "r"(a[2]), "r"(a[3]), "r"(b0), "r"(b1));
}

// ---------------------------------------------------------------------------
// Unified split: hidden + Wq + Wk + Wv -> bf16 hi/lo, one launch.
// ---------------------------------------------------------------------------
#define HN8 ((GM * GK) / 8)
#define WN8 ((GN * GK) / 8)
#define TOTN8 (HN8 + 3 * WN8)

__global__ __launch_bounds__(256) void split_all(
    const float* __restrict__ hidden,
    const float* __restrict__ Wq,
    const float* __restrict__ Wk,
    const float* __restrict__ Wv)
{
    int i = blockIdx.x * blockDim.x + threadIdx.x;
    if (i >= TOTN8) return;

    const float* src;
    __nv_bfloat16 *hi, *lo;
    size_t off;
    if (i < HN8) {
        src = hidden; hi = g_ah; lo = g_al; off = (size_t)i * 8;
    } else {
        int j = i - HN8;
        int w = j / WN8;
        off = (size_t)(j - w * WN8) * 8;
        src = (w == 0) ? Wq : (w == 1) ? Wk : Wv;
        hi = g_wh[w]; lo = g_wl[w];
    }

    const float4* xp = (const float4*)(src + off);
    float4 a = xp[0], b = xp[1];
    float f[8] = {a.x, a.y, a.z, a.w, b.x, b.y, b.z, b.w};
    __align__(16) __nv_bfloat16 h[8];
    __align__(16) __nv_bfloat16 l[8];
    #pragma unroll
    for (int j = 0; j < 8; j++) {
        h[j] = __float2bfloat16(f[j]);
        l[j] = __float2bfloat16(f[j] - __bfloat162float(h[j]));
    }
    *(uint4*)(hi + off) = *(uint4*)h;
    *(uint4*)(lo + off) = *(uint4*)l;
}

// ---------------------------------------------------------------------------
// QKV GEMM via mma.sync, 3-term bf16 split, fp32 accum.
// Block tile 256(M) x 128(N), K-chunk 64, 2-stage cp.async.
// 8 warps, each 64x64 warp tile (acc = 128 regs).
// ---------------------------------------------------------------------------
#define TM 256
#define TN 128
#define TK 64
#define NCHUNK (GK / TK)                 // 16
#define AT_B  (TM * TK * 2)              // 32768 (one A half-tile)
#define BT_B  (TN * TK * 2)              // 16384 (one B half-tile)
#define STAGE_B (2 * AT_B + 2 * BT_B)    // 98304
#define OFF_AH 0
#define OFF_AL AT_B
#define OFF_BH (2 * AT_B)
#define OFF_BL (2 * AT_B + BT_B)
#define GSMEM  (2 * STAGE_B)             // 196608

__global__ __launch_bounds__(256, 1) void qkv_gemm_mma(
    const float* __restrict__ bias_q,
    const float* __restrict__ bias_k,
    const float* __restrict__ bias_v)
{
    extern __shared__ __align__(1024) char sb[];

    const int z  = blockIdx.z;
    const int bm = blockIdx.y * TM;
    const int bn = blockIdx.x * TN;

    const __nv_bfloat16* Ah = g_ah;
    const __nv_bfloat16* Al = g_al;
    const __nv_bfloat16* Bh = g_wh[z];
    const __nv_bfloat16* Bl = g_wl[z];
    const float* bias = (z == 0) ? bias_q : (z == 1) ? bias_k : bias_v;
    float* Cout = (z == 0) ? g_q : (z == 1) ? g_k : g_v;

    const int tid  = threadIdx.x;
    const int wid  = tid >> 5;
    const int lane = tid & 31;
    const int wm   = (wid >> 1) * 64;   // 0,64,128,192
    const int wn   = (wid & 1) * 64;    // 0,64

    const uint32_t sbase = smem_u32(sb);

    auto load_chunk = [&](int c, int buf) {
        const int kc = c * TK;
        const uint32_t stage = sbase + buf * STAGE_B;
        // A halves: 256 rows x 64 cols -> 2048 cp16, 8 per thread per half
        #pragma unroll
        for (int half = 0; half < 2; half++) {
            const __nv_bfloat16* src = half ? Al : Ah;
            uint32_t dtile = stage + (half ? OFF_AL : OFF_AH);
            #pragma unroll
            for (int i = 0; i < 8; i++) {
                int idx = tid + i * 256;       // 0..2047
                int row = idx >> 3;            // 0..255
                int v   = idx & 7;
                uint32_t off = (uint32_t)(row << 7) + (uint32_t)(v << 4);
                off ^= ((uint32_t)(row & 7) << 4);
                cp16(dtile + off, src + (size_t)(bm + row) * GK + kc + v * 8);
            }
        }
        // B halves: 128 rows x 64 cols -> 1024 cp16, 4 per thread per half
        #pragma unroll
        for (int half = 0; half < 2; half++) {
            const __nv_bfloat16* src = half ? Bl : Bh;
            uint32_t dtile = stage + (half ? OFF_BL : OFF_BH);
            #pragma unroll
            for (int i = 0; i < 4; i++) {
                int idx = tid + i * 256;       // 0..1023
                int row = idx >> 3;            // 0..127
                int v   = idx & 7;
                uint32_t off = (uint32_t)(row << 7) + (uint32_t)(v << 4);
                off ^= ((uint32_t)(row & 7) << 4);
                cp16(dtile + off, src + (size_t)(bn + row) * GK + kc + v * 8);
            }
        }
    };

    float acc[4][8][4];
    #pragma unroll
    for (int f = 0; f < 4; f++)
        #pragma unroll
        for (int g = 0; g < 8; g++)
            #pragma unroll
            for (int j = 0; j < 4; j++) acc[f][g][j] = 0.f;

    const int a_row_l = lane & 15;
    const int a_kb_l  = (lane >> 4) << 4;
    const int b_row_l = (lane & 7) + ((lane >> 4) << 3);
    const int b_kb_l  = ((lane >> 3) & 1) << 4;

    load_chunk(0, 0);
    CP_COMMIT();

    for (int c = 0; c < NCHUNK; c++) {
        const int buf = c & 1;
        if (c + 1 < NCHUNK) {
            load_chunk(c + 1, buf ^ 1);
            CP_COMMIT();
            CP_WAIT1();
        } else {
            CP_WAIT0();
        }
        __syncthreads();

        const uint32_t stage  = sbase + buf * STAGE_B;
        const uint32_t baseAh = stage + OFF_AH;
        const uint32_t baseAl = stage + OFF_AL;
        const uint32_t baseBh = stage + OFF_BH;
        const uint32_t baseBl = stage + OFF_BL;

        #pragma unroll
        for (int s = 0; s < 4; s++) {
            uint32_t aH[4][4], aL[4][4], bH[4][4], bL[4][4];
            const uint32_t cbA = (uint32_t)(s * 32 + a_kb_l);
            const uint32_t cbB = (uint32_t)(s * 32 + b_kb_l);
            #pragma unroll
            for (int f = 0; f < 4; f++) {
                int row = wm + f * 16 + a_row_l;
                uint32_t off = (uint32_t)(row << 7) + (cbA ^ ((uint32_t)(row & 7) << 4));
                ldsm4(aH[f], baseAh + off);
                ldsm4(aL[f], baseAl + off);
            }
            #pragma unroll
            for (int g16 = 0; g16 < 4; g16++) {
                int row = wn + g16 * 16 + b_row_l;
                uint32_t off = (uint32_t)(row << 7) + (cbB ^ ((uint32_t)(row & 7) << 4));
                ldsm4(bH[g16], baseBh + off);
                ldsm4(bL[g16], baseBl + off);
            }
            #pragma unroll
            for (int f = 0; f < 4; f++) {
                #pragma unroll
                for (int g16 = 0; g16 < 4; g16++) {
                    #pragma unroll
                    for (int p = 0; p < 2; p++) {
                        float* cc = acc[f][g16 * 2 + p];
                        mma16816(cc, aH[f], bH[g16][2*p], bH[g16][2*p+1]);
                        mma16816(cc, aH[f], bL[g16][2*p], bL[g16][2*p+1]);
                        mma16816(cc, aL[f], bH[g16][2*p], bH[g16][2*p+1]);
                    }
                }
            }
        }
        __syncthreads();
    }

    // ---- epilogue: bias + fp32 store ----
    #pragma unroll
    for (int f = 0; f < 4; f++) {
        #pragma unroll
        for (int g = 0; g < 8; g++) {
            int row = bm + wm + f * 16 + (lane >> 2);
            int col = bn + wn + g * 8 + (lane & 3) * 2;
            float b0 = bias[col], b1 = bias[col + 1];
            float2 o0 = make_float2(acc[f][g][0] + b0, acc[f][g][1] + b1);
            float2 o1 = make_float2(acc[f][g][2] + b0, acc[f][g][3] + b1);
            *(float2*)(Cout + (size_t)row * GN + col)       = o0;
            *(float2*)(Cout + (size_t)(row + 8) * GN + col) = o1;
        }
    }
}

// ---------------------------------------------------------------------------
// Global attention pass 1: grid (GCH, 64), 512 keys per block.
// ---------------------------------------------------------------------------
#define SCHUNK (S / GCH)   // 512

__global__ __launch_bounds__(256) void gattn_part(const float* __restrict__ mask)
{
    const int ch = blockIdx.x;
    const int bh = blockIdx.y;
    const int b  = bh / NH;
    const int h  = bh % NH;

    __shared__ float sq[D];
    __shared__ float sp[SCHUNK];
    __shared__ float red[8];
    __shared__ float vwarp[8][D];

    const int tid  = threadIdx.x;
    const int lane = tid & 31;
    const int w    = tid >> 5;

    if (tid < D) sq[tid] = g_q[((size_t)b * S) * H + h * D + tid];
    __syncthreads();

    const float q0 = sq[2 * lane];
    const float q1 = sq[2 * lane + 1];
    const int sbase = ch * SCHUNK + w * (SCHUNK / 8);

    for (int i = 0; i < SCHUNK / 8; i++) {
        int s = sbase + i;
        float2 k2 = ((const float2*)(g_k + ((size_t)b * S + s) * H + h * D))[lane];
        float ps = q0 * k2.x + q1 * k2.y;
        #pragma unroll
        for (int o = 16; o; o >>= 1) ps += __shfl_xor_sync(~0u, ps, o);
        if (lane == 0)
            sp[w * (SCHUNK / 8) + i] = ps * SCALE + mask[(size_t)b * S + s];
    }
    __syncthreads();

    float lm = fmaxf(sp[tid], sp[tid + 256]);
    #pragma unroll
    for (int o = 16; o; o >>= 1) lm = fmaxf(lm, __shfl_xor_sync(~0u, lm, o));
    if (lane == 0) red[w] = lm;
    __syncthreads();
    float bm = red[0];
    #pragma unroll
    for (int ww = 1; ww < 8; ww++) bm = fmaxf(bm, red[ww]);
    __syncthreads();

    float e0 = expf(sp[tid] - bm);
    float e1 = expf(sp[tid + 256] - bm);
    sp[tid] = e0; sp[tid + 256] = e1;
    float ls = e0 + e1;
    #pragma unroll
    for (int o = 16; o; o >>= 1) ls += __shfl_xor_sync(~0u, ls, o);
    if (lane == 0) red[w] = ls;
    __syncthreads();
    float bsum = 0.f;
    #pragma unroll
    for (int ww = 0; ww < 8; ww++) bsum += red[ww];

    float a0 = 0.f, a1 = 0.f;
    for (int i = 0; i < SCHUNK / 8; i++) {
        int s = sbase + i;
        float p = sp[w * (SCHUNK / 8) + i];
        float2 v2 = ((const float2*)(g_v + ((size_t)b * S + s) * H + h * D))[lane];
        a0 = fmaf(p, v2.x, a0);
        a1 = fmaf(p, v2.y, a1);
    }
    vwarp[w][2 * lane]     = a0;
    vwarp[w][2 * lane + 1] = a1;
    __syncthreads();

    if (tid < D) {
        float vs = 0.f;
        #pragma unroll
        for (int ww = 0; ww < 8; ww++) vs += vwarp[ww][tid];
        g_pvac[bh][ch][tid] = vs;
    }
    if (tid == 0) {
        g_pmax[bh][ch] = bm;
        g_psum[bh][ch] = bsum;
    }
}

__global__ __launch_bounds__(64) void gattn_combine(float* __restrict__ out)
{
    const int bh = blockIdx.x;
    const int b  = bh / NH;
    const int h  = bh % NH;
    const int tid = threadIdx.x;

    float M = -INFINITY;
    #pragma unroll
    for (int c = 0; c < GCH; c++) M = fmaxf(M, g_pmax[bh][c]);
    float denom = 0.f, vs = 0.f;
    #pragma unroll
    for (int c = 0; c < GCH; c++) {
        float sc = expf(g_pmax[bh][c] - M);
        denom += g_psum[bh][c] * sc;
        vs    += g_pvac[bh][c][tid] * sc;
    }
    out[((size_t)b * S) * H + h * D + tid] = vs / denom;
}

// ---------------------------------------------------------------------------
// Local attention: one warp per (b, h, s), s in 1..S-1
// ---------------------------------------------------------------------------
__global__ __launch_bounds__(256) void local_attn(float* __restrict__ out)
{
    const int gwarp = (blockIdx.x * blockDim.x + threadIdx.x) >> 5;
    const int lane  = threadIdx.x & 31;
    const int total = B * NH * (S - 1);
    if (gwarp >= total) return;

    const int s1 = gwarp % (S - 1);
    const int s  = s1 + 1;
    const int bh = gwarp / (S - 1);
    const int h  = bh % NH;
    const int b  = bh / NH;

    const size_t base_s = ((size_t)b * S + s) * H + (size_t)h * D;
    const size_t base_0 = ((size_t)b * S + 0) * H + (size_t)h * D;

    float2 q2 = ((const float2*)(g_q + base_s))[lane];
    float2 k2 = ((const float2*)(g_k + base_s))[lane];
    float2 k0 = ((const float2*)(g_k + base_0))[lane];

    float ps = q2.x * k2.x + q2.y * k2.y;
    float pg = q2.x * k0.x + q2.y * k0.y;
    #pragma unroll
    for (int o = 16; o; o >>= 1) {
        ps += __shfl_xor_sync(~0u, ps, o);
        pg += __shfl_xor_sync(~0u, pg, o);
    }
    ps *= SCALE;
    pg *= SCALE;

    float m  = fmaxf(ps, pg);
    float e0 = expf(ps - m);
    float e1 = expf(pg - m);
    float inv = 1.f / (e0 + e1);
    float p0 = e0 * inv;
    float p1 = e1 * inv;

    float2 v2 = ((const float2*)(g_v + base_s))[lane];
    float2 v0 = ((const float2*)(g_v + base_0))[lane];
    float2 o2;
    o2.x = p0 * v2.x + p1 * v0.x;
    o2.y = p0 * v2.y + p1 * v0.y;
    ((float2*)(out + base_s))[lane] = o2;

    if (lane == 0) {
        size_t li = CTX_ELEMS + ((size_t)bh * (S - 1) + s1) * 2;
        out[li]     = p0;
        out[li + 1] = p1;
    }
}

// ---------------------------------------------------------------------------
extern "C" void kernel_launch(void* const* d_in, const int* in_sizes, int n_in,
                              void* d_out, int out_size)
{
    const float* hidden = (const float*)d_in[0];
    const float* mask   = (const float*)d_in[1];
    const float* Wq     = (const float*)d_in[2];
    const float* bq     = (const float*)d_in[3];
    const float* Wk     = (const float*)d_in[4];
    const float* bk     = (const float*)d_in[5];
    const float* Wv     = (const float*)d_in[6];
    const float* bv     = (const float*)d_in[7];
    float* out = (float*)d_out;

    split_all<<<(TOTN8 + 255) / 256, 256>>>(hidden, Wq, Wk, Wv);

    cudaFuncSetAttribute(qkv_gemm_mma, cudaFuncAttributeMaxDynamicSharedMemorySize, GSMEM);
    dim3 ggrid(GN / TN, GM / TM, 3);   // (8, 64, 3) = 1536 CTAs
    qkv_gemm_mma<<<ggrid, 256, GSMEM>>>(bq, bk, bv);

    dim3 pgrid(GCH, B * NH);
    gattn_part<<<pgrid, 256>>>(mask);
    gattn_combine<<<B * NH, 64>>>(out);

    const int totalWarps = B * NH * (S - 1);
    const int blocks = (totalWarps * 32 + 255) / 256;
    local_attn<<<blocks, 256>>>(out);
}